// round 13
// baseline (speedup 1.0000x reference)
#include <cuda_runtime.h>
#include <math.h>
#include <stdint.h>

#define N_NODES 3072
#define F_IN 512
#define NHID 64
#define NHEADS 4
#define NGRAPH 3
#define NCLASS 16
#define NGH (NGRAPH * NHEADS)
#define DCAT (NHEADS * NHID)   // 256
#define ALPHA 0.2f

// -------- scratch (no allocations allowed) --------
__device__ uint32_t d_xtf[48 * 8 * 4096];                    // x in tf32, A-swizzled tiles
__device__ uint32_t d_Wtf[NGH * 8 * 4096];                   // W in tf32, B-swizzled tiles
__device__ uint32_t d_Whbf[NGH * 48 * 2048];                 // bf16x2, tile-swizzled
__device__ float2 d_ef1[NGH * N_NODES];                      // (e^f1, e^{0.2 f1})
__device__ float2 d_ef2[NGH * N_NODES];                      // (e^f2, e^{0.2 f2})
__device__ float d_hcat[NGRAPH * N_NODES * DCAT];            // [g][n][h*64+o]
__device__ unsigned long long d_abits[NGRAPH * N_NODES * 48]; // bitpacked adj

// ---------- helpers ----------
__device__ __forceinline__ uint32_t f2tf32(float f) {
    uint32_t u;
    asm("cvt.rna.tf32.f32 %0, %1;" : "=r"(u) : "f"(f));
    return u;
}
__device__ __forceinline__ uint32_t pkbf2(float lo, float hi) {
    uint32_t r;
    asm("cvt.rn.bf16x2.f32 %0, %1, %2;" : "=r"(r) : "f"(hi), "f"(lo));
    return r;
}
__device__ __forceinline__ void mma_tf32(float d[4], uint32_t a0, uint32_t a1,
                                         uint32_t a2, uint32_t a3,
                                         uint32_t b0, uint32_t b1) {
    asm volatile(
        "mma.sync.aligned.m16n8k8.row.col.f32.tf32.tf32.f32 "
        "{%0,%1,%2,%3},{%4,%5,%6,%7},{%8,%9},{%0,%1,%2,%3};\n"
        : "+f"(d[0]), "+f"(d[1]), "+f"(d[2]), "+f"(d[3])
        : "r"(a0), "r"(a1), "r"(a2), "r"(a3), "r"(b0), "r"(b1));
}
__device__ __forceinline__ void mma_bf16(float d[4], uint32_t a0, uint32_t a1,
                                         uint32_t a2, uint32_t a3,
                                         uint32_t b0, uint32_t b1) {
    asm volatile(
        "mma.sync.aligned.m16n8k16.row.col.f32.bf16.bf16.f32 "
        "{%0,%1,%2,%3},{%4,%5,%6,%7},{%8,%9},{%0,%1,%2,%3};\n"
        : "+f"(d[0]), "+f"(d[1]), "+f"(d[2]), "+f"(d[3])
        : "r"(a0), "r"(a1), "r"(a2), "r"(a3), "r"(b0), "r"(b1));
}
// word-granular swizzle: word (kp, n) of a [32|64]x64 word tile.
__device__ __forceinline__ int bswz(int k, int n) {
    return k * 64 + (n ^ ((k & 3) << 3));
}
__device__ __forceinline__ int aswz(int r, int c) {
    return r * 64 + (c ^ ((r & 3) << 3) ^ (r & 4));
}
// cp.async
__device__ __forceinline__ void cpa16(void* smem_dst, const void* gsrc) {
    uint32_t d = (uint32_t)__cvta_generic_to_shared(smem_dst);
    asm volatile("cp.async.ca.shared.global [%0], [%1], 16;\n" :: "r"(d), "l"(gsrc));
}
__device__ __forceinline__ void cpa_commit() {
    asm volatile("cp.async.commit_group;\n");
}
template <int NW> __device__ __forceinline__ void cpa_wait() {
    asm volatile("cp.async.wait_group %0;\n" :: "n"(NW));
}

// ============================================================
// K0: bitpack adj (int32 0/1 -> 64-bit masks). One warp per row.
// ============================================================
__global__ __launch_bounds__(256) void k0_pack(const int* __restrict__ adj) {
    const int row = blockIdx.x * 8 + (threadIdx.x >> 5);  // g*N + n
    const int lane = threadIdx.x & 31;
    const int* arow = adj + (size_t)row * N_NODES;
    unsigned long long* brow = d_abits + (size_t)row * 48;
    for (int j = 0; j < 48; j++) {
        unsigned lo = __ballot_sync(0xffffffffu, arow[j * 64 + lane] != 0);
        unsigned hi = __ballot_sync(0xffffffffu, arow[j * 64 + 32 + lane] != 0);
        if (lane == 0) brow[j] = ((unsigned long long)hi << 32) | lo;
    }
}

// ============================================================
// K0x / K0w: one-time tf32 conversion + swizzle of x and W
// ============================================================
__global__ __launch_bounds__(128) void k0x(const float* __restrict__ x) {
    const int nt = blockIdx.x, kt = blockIdx.y, t = threadIdx.x;
    uint32_t* dst = d_xtf + ((size_t)nt * 8 + kt) * 4096;
#pragma unroll
    for (int it = 0; it < 8; it++) {
        int idx = t + it * 128;
        int r = idx >> 4, c4 = (idx & 15) * 4;
        float4 v = *(const float4*)(x + (size_t)(nt * 64 + r) * F_IN + kt * 64 + c4);
        uint4 u = make_uint4(f2tf32(v.x), f2tf32(v.y), f2tf32(v.z), f2tf32(v.w));
        *(uint4*)&dst[aswz(r, c4)] = u;
    }
}
__global__ __launch_bounds__(128) void k0w(const float* __restrict__ W) {
    const int gh = blockIdx.x, kt = blockIdx.y, t = threadIdx.x;
    uint32_t* dst = d_Wtf + ((size_t)gh * 8 + kt) * 4096;
    const float* Wg = W + (size_t)gh * F_IN * NHID + (size_t)kt * 64 * NHID;
#pragma unroll
    for (int it = 0; it < 8; it++) {
        int idx = t + it * 128;
        int k = idx >> 4, n4 = (idx & 15) * 4;
        float4 v = *(const float4*)(Wg + (size_t)k * NHID + n4);
        uint4 u = make_uint4(f2tf32(v.x), f2tf32(v.y), f2tf32(v.z), f2tf32(v.w));
        *(uint4*)&dst[bswz(k, n4)] = u;
    }
}

// ============================================================
// K1: Wh = x @ W via tf32 mma on pre-converted tiles.
// cp.async double-buffered pure copies (no cvt / STS in loop).
// Epilogue: f1/f2 exp factors + bf16 pack for k2.
// grid (48, 12), 128 thr, 66 KB dynamic smem.
// ============================================================
__global__ __launch_bounds__(128) void k1_wh(const float* __restrict__ a) {
    extern __shared__ uint32_t dsm[];
    uint32_t* As0 = dsm;            uint32_t* As1 = dsm + 4096;
    uint32_t* Bs0 = dsm + 8192;     uint32_t* Bs1 = dsm + 12288;
    float* sa = (float*)(dsm + 16384);
    const int gh = blockIdx.y, bx = blockIdx.x;
    const int t = threadIdx.x, lane = t & 31, w = t >> 5;
    const int gi = lane >> 2, q = lane & 3;
    sa[t] = a[gh * 128 + t];

    const uint32_t* xsrc = d_xtf + (size_t)bx * 8 * 4096;
    const uint32_t* wsrc = d_Wtf + (size_t)gh * 8 * 4096;

    float acc[8][4];
#pragma unroll
    for (int nt = 0; nt < 8; nt++)
#pragma unroll
        for (int j = 0; j < 4; j++) acc[nt][j] = 0.f;

    // prologue: stage tile 0
#pragma unroll
    for (int it = 0; it < 8; it++) {
        int s4 = (t + it * 128) * 4;
        cpa16(&As0[s4], xsrc + s4);
        cpa16(&Bs0[s4], wsrc + s4);
    }
    cpa_commit();

    for (int kt = 0; kt < 8; kt++) {
        uint32_t* As = (kt & 1) ? As1 : As0;
        uint32_t* Bs = (kt & 1) ? Bs1 : Bs0;
        if (kt < 7) {
            uint32_t* An = (kt & 1) ? As0 : As1;
            uint32_t* Bn = (kt & 1) ? Bs0 : Bs1;
            const uint32_t* xs2 = xsrc + (size_t)(kt + 1) * 4096;
            const uint32_t* ws2 = wsrc + (size_t)(kt + 1) * 4096;
#pragma unroll
            for (int it = 0; it < 8; it++) {
                int s4 = (t + it * 128) * 4;
                cpa16(&An[s4], xs2 + s4);
                cpa16(&Bn[s4], ws2 + s4);
            }
            cpa_commit();
            cpa_wait<1>();
        } else {
            cpa_wait<0>();
        }
        __syncthreads();
#pragma unroll
        for (int kk = 0; kk < 8; kk++) {
            uint32_t a0 = As[aswz(16 * w + gi,     8 * kk + q)];
            uint32_t a1 = As[aswz(16 * w + gi + 8, 8 * kk + q)];
            uint32_t a2 = As[aswz(16 * w + gi,     8 * kk + q + 4)];
            uint32_t a3 = As[aswz(16 * w + gi + 8, 8 * kk + q + 4)];
#pragma unroll
            for (int nt = 0; nt < 8; nt++) {
                uint32_t b0 = Bs[bswz(8 * kk + q,     8 * nt + gi)];
                uint32_t b1 = Bs[bswz(8 * kk + q + 4, 8 * nt + gi)];
                mma_tf32(acc[nt], a0, a1, a2, a3, b0, b1);
            }
        }
        __syncthreads();
    }

    const int R0 = bx * 64 + 16 * w + gi, R1 = R0 + 8;

    // ---- f1/f2 (full-precision fragments), then exp forms ----
    float p10 = 0.f, p20 = 0.f, p11 = 0.f, p21 = 0.f;
#pragma unroll
    for (int nt = 0; nt < 8; nt++) {
        int c0 = 8 * nt + 2 * q;
        p10 += acc[nt][0] * sa[c0]      + acc[nt][1] * sa[c0 + 1];
        p20 += acc[nt][0] * sa[64 + c0] + acc[nt][1] * sa[64 + c0 + 1];
        p11 += acc[nt][2] * sa[c0]      + acc[nt][3] * sa[c0 + 1];
        p21 += acc[nt][2] * sa[64 + c0] + acc[nt][3] * sa[64 + c0 + 1];
    }
#pragma unroll
    for (int off = 1; off < 4; off <<= 1) {
        p10 += __shfl_xor_sync(0xffffffffu, p10, off);
        p20 += __shfl_xor_sync(0xffffffffu, p20, off);
        p11 += __shfl_xor_sync(0xffffffffu, p11, off);
        p21 += __shfl_xor_sync(0xffffffffu, p21, off);
    }
    if (q == 0) {
        d_ef1[(size_t)gh * N_NODES + R0] = make_float2(__expf(p10), __expf(ALPHA * p10));
        d_ef2[(size_t)gh * N_NODES + R0] = make_float2(__expf(p20), __expf(ALPHA * p20));
        d_ef1[(size_t)gh * N_NODES + R1] = make_float2(__expf(p11), __expf(ALPHA * p11));
        d_ef2[(size_t)gh * N_NODES + R1] = make_float2(__expf(p21), __expf(ALPHA * p21));
    }

    // ---- bf16 pack, adjacent-row pairing via shfl, swizzled store ----
    uint32_t* dst = d_Whbf + ((size_t)gh * 48 + bx) * 2048;
    const bool even = (gi & 1) == 0;
    const int kp = 8 * w + (gi >> 1) + (even ? 0 : 4);
#pragma unroll
    for (int nt = 0; nt < 8; nt++) {
        float o0 = __shfl_xor_sync(0xffffffffu, acc[nt][0], 4);
        float o1 = __shfl_xor_sync(0xffffffffu, acc[nt][1], 4);
        float o2 = __shfl_xor_sync(0xffffffffu, acc[nt][2], 4);
        float o3 = __shfl_xor_sync(0xffffffffu, acc[nt][3], 4);
        uint32_t w0, w1;
        if (even) { w0 = pkbf2(acc[nt][0], o0); w1 = pkbf2(acc[nt][1], o1); }
        else      { w0 = pkbf2(o2, acc[nt][2]); w1 = pkbf2(o3, acc[nt][3]); }
        int c = 8 * nt + 2 * q;
        int o = bswz(kp, c);
        *(uint2*)&dst[o] = make_uint2(w0, w1);
    }
}

// ============================================================
// K2: fused attention. exp(leaky(s)) = max(ea*eb, fa*fb) -- zero MUFU
// in the hot loop. cp.async double-buffered staging of pre-packed bf16 Wh.
// grid (48, NHEADS, NGRAPH), 128 thr.
// ============================================================
__global__ __launch_bounds__(128) void k2_attn() {
    __shared__ uint32_t Whs[2][2048];
    __shared__ float2 efs[2][64];
    const int g_ = blockIdx.z, h = blockIdx.y;
    const int gh = g_ * NHEADS + h;
    const int n0 = blockIdx.x * 64;
    const int t = threadIdx.x, lane = t & 31, w = t >> 5;
    const int gi = lane >> 2, q = lane & 3;
    const int qx = q << 3;
    const int R0 = n0 + 16 * w + gi, R1 = R0 + 8;

    const uint32_t* Wsrc = d_Whbf + (size_t)gh * 48 * 2048;
    const float2* ef2g = d_ef2 + (size_t)gh * N_NODES;
    const unsigned long long* bits0 = d_abits + ((size_t)g_ * N_NODES + R0) * 48;
    const unsigned long long* bits1 = d_abits + ((size_t)g_ * N_NODES + R1) * 48;
    const float2 ef1a = d_ef1[(size_t)gh * N_NODES + R0];
    const float2 ef1b = d_ef1[(size_t)gh * N_NODES + R1];
    const float ea0 = ef1a.x, fa0 = ef1a.y, ea1 = ef1b.x, fa1 = ef1b.y;

    int nxs[8];
#pragma unroll
    for (int nt = 0; nt < 8; nt++) nxs[nt] = (8 * nt + gi) ^ qx;

    float acc[8][4];
#pragma unroll
    for (int nt = 0; nt < 8; nt++)
#pragma unroll
        for (int j = 0; j < 4; j++) acc[nt][j] = 0.f;
    float rs0 = 0.f, rs1 = 0.f;

    // stage tile 0
    {
        const uint32_t* src = Wsrc;
#pragma unroll
        for (int it = 0; it < 4; it++)
            cpa16(&Whs[0][(t + it * 128) * 4], src + (t + it * 128) * 4);
        if (t < 32) cpa16(&efs[0][t * 2], ef2g + t * 2);
        cpa_commit();
    }

    for (int mt = 0; mt < 48; mt++) {
        const int buf = mt & 1;
        if (mt + 1 < 48) {
            const uint32_t* src = Wsrc + (size_t)(mt + 1) * 2048;
#pragma unroll
            for (int it = 0; it < 4; it++)
                cpa16(&Whs[buf ^ 1][(t + it * 128) * 4], src + (t + it * 128) * 4);
            if (t < 32) cpa16(&efs[buf ^ 1][t * 2], ef2g + (mt + 1) * 64 + t * 2);
            cpa_commit();
            cpa_wait<1>();
        } else {
            cpa_wait<0>();
        }
        __syncthreads();

        const uint32_t m0lo = (uint32_t)bits0[mt], m0hi = (uint32_t)(bits0[mt] >> 32);
        const uint32_t m1lo = (uint32_t)bits1[mt], m1hi = (uint32_t)(bits1[mt] >> 32);

#pragma unroll
        for (int kt = 0; kt < 4; kt++) {
            const int cb = 16 * kt + 2 * q;
            const float2 e0 = efs[buf][cb],     e1 = efs[buf][cb + 1];
            const float2 e8 = efs[buf][cb + 8], e9 = efs[buf][cb + 9];
            const uint32_t m0b = (kt < 2) ? (m0lo >> cb) : (m0hi >> (cb - 32));
            const uint32_t m1b = (kt < 2) ? (m1lo >> cb) : (m1hi >> (cb - 32));

            float p00 = fmaxf(ea0 * e0.x, fa0 * e0.y);
            float p01 = fmaxf(ea0 * e1.x, fa0 * e1.y);
            float p02 = fmaxf(ea0 * e8.x, fa0 * e8.y);
            float p03 = fmaxf(ea0 * e9.x, fa0 * e9.y);
            float p10 = fmaxf(ea1 * e0.x, fa1 * e0.y);
            float p11 = fmaxf(ea1 * e1.x, fa1 * e1.y);
            float p12 = fmaxf(ea1 * e8.x, fa1 * e8.y);
            float p13 = fmaxf(ea1 * e9.x, fa1 * e9.y);

            p00 = (m0b & 1u)     ? p00 : 0.f;
            p01 = (m0b & 2u)     ? p01 : 0.f;
            p02 = (m0b & 0x100u) ? p02 : 0.f;
            p03 = (m0b & 0x200u) ? p03 : 0.f;
            p10 = (m1b & 1u)     ? p10 : 0.f;
            p11 = (m1b & 2u)     ? p11 : 0.f;
            p12 = (m1b & 0x100u) ? p12 : 0.f;
            p13 = (m1b & 0x200u) ? p13 : 0.f;

            rs0 += (p00 + p01) + (p02 + p03);
            rs1 += (p10 + p11) + (p12 + p13);

            const uint32_t a0 = pkbf2(p00, p01);
            const uint32_t a1 = pkbf2(p10, p11);
            const uint32_t a2 = pkbf2(p02, p03);
            const uint32_t a3 = pkbf2(p12, p13);
            const int kb0 = (8 * kt + q) * 64;
            const int kb1 = kb0 + 256;
#pragma unroll
            for (int nt = 0; nt < 8; nt++) {
                uint32_t b0 = Whs[buf][kb0 + nxs[nt]];
                uint32_t b1 = Whs[buf][kb1 + nxs[nt]];
                mma_bf16(acc[nt], a0, a1, a2, a3, b0, b1);
            }
        }
        __syncthreads();
    }

    rs0 += __shfl_xor_sync(0xffffffffu, rs0, 1);
    rs0 += __shfl_xor_sync(0xffffffffu, rs0, 2);
    rs1 += __shfl_xor_sync(0xffffffffu, rs1, 1);
    rs1 += __shfl_xor_sync(0xffffffffu, rs1, 2);

    const float inv0 = 1.0f / rs0, inv1 = 1.0f / rs1;
    float* outg = d_hcat + (size_t)g_ * N_NODES * DCAT;
#pragma unroll
    for (int nt = 0; nt < 8; nt++) {
        float v0 = acc[nt][0] * inv0, v1 = acc[nt][1] * inv0;
        float v2 = acc[nt][2] * inv1, v3 = acc[nt][3] * inv1;
        v0 = v0 > 0.f ? v0 : (__expf(v0) - 1.f);
        v1 = v1 > 0.f ? v1 : (__expf(v1) - 1.f);
        v2 = v2 > 0.f ? v2 : (__expf(v2) - 1.f);
        v3 = v3 > 0.f ? v3 : (__expf(v3) - 1.f);
        *(float2*)(outg + (size_t)R0 * DCAT + h * NHID + 8 * nt + 2 * q) =
            make_float2(v0, v1);
        *(float2*)(outg + (size_t)R1 * DCAT + h * NHID + 8 * nt + 2 * q) =
            make_float2(v2, v3);
    }
}

// ============================================================
// K3: xi = elu(hcat @ W_int^T + b_int) -> @ W_fus^T + b_fus -> log_softmax
// cp.async stages weights AND the block's 8 hcat rows into smem;
// compute runs entirely from smem. thread = (node, class). grid 384 x 128.
// ============================================================
__global__ __launch_bounds__(128) void k3_out(const float* __restrict__ Wint,
                                              const float* __restrict__ bint,
                                              const float* __restrict__ Wfus,
                                              const float* __restrict__ bfus,
                                              float* __restrict__ out) {
    __shared__ __align__(16) float sWi[NCLASS][260];   // natural [c][k]
    __shared__ __align__(16) float sWf[NCLASS * 52];
    __shared__ __align__(16) float sh[NGRAPH][8][DCAT];
    __shared__ float sXi[8 * 48];
    __shared__ float sbi[NCLASS], sbf[NCLASS];
    const int t = threadIdx.x;
    const int n0 = blockIdx.x * 8;

    // stage everything with one cp.async wave
    for (int s = t; s < 1024; s += 128) {          // W_int: 16x256
        int c = s >> 6, ks = (s & 63) * 4;
        cpa16(&sWi[c][ks], Wint + c * DCAT + ks);
    }
    for (int s = t; s < 192; s += 128) {           // W_fus: 16x48
        int c = s / 12, js = (s % 12) * 4;
        cpa16(&sWf[c * 52 + js], Wfus + c * 48 + js);
    }
    for (int s = t; s < 1536; s += 128) {          // hcat: 3 x 8 x 256
        int g = s / 512, rem = s - g * 512;
        int node = rem >> 6, ks = (rem & 63) * 4;
        cpa16(&sh[g][node][ks],
              d_hcat + ((size_t)g * N_NODES + n0 + node) * DCAT + ks);
    }
    cpa_commit();
    if (t < NCLASS) { sbi[t] = bint[t]; sbf[t] = bfus[t]; }
    cpa_wait<0>();
    __syncthreads();

    const int nb = t >> 4, c = t & 15;
    const float* wc = sWi[c];

#pragma unroll
    for (int g = 0; g < NGRAPH; g++) {
        const float* hp = sh[g][nb];
        float a0 = 0.f, a1 = 0.f, a2 = 0.f, a3 = 0.f;
#pragma unroll 4
        for (int k0 = 0; k0 < DCAT; k0 += 16) {
            float4 h0 = *(const float4*)(hp + k0);
            float4 h1 = *(const float4*)(hp + k0 + 4);
            float4 h2 = *(const float4*)(hp + k0 + 8);
            float4 h3 = *(const float4*)(hp + k0 + 12);
            float4 w0 = *(const float4*)(wc + k0);
            float4 w1 = *(const float4*)(wc + k0 + 4);
            float4 w2 = *(const float4*)(wc + k0 + 8);
            float4 w3 = *(const float4*)(wc + k0 + 12);
            a0 += h0.x * w0.x + h0.y * w0.y + h0.z * w0.z + h0.w * w0.w;
            a1 += h1.x * w1.x + h1.y * w1.y + h1.z * w1.z + h1.w * w1.w;
            a2 += h2.x * w2.x + h2.y * w2.y + h2.z * w2.z + h2.w * w2.w;
            a3 += h3.x * w3.x + h3.y * w3.y + h3.z * w3.z + h3.w * w3.w;
        }
        float xv = (a0 + a1) + (a2 + a3) + sbi[c];
        sXi[nb * 48 + g * 16 + c] = xv > 0.f ? xv : (__expf(xv) - 1.f);
    }
    __syncthreads();

    float o = sbf[c];
#pragma unroll
    for (int j = 0; j < 48; j++) o += sXi[nb * 48 + j] * sWf[c * 52 + j];

    float m = o;
#pragma unroll
    for (int off = 1; off < 16; off <<= 1)
        m = fmaxf(m, __shfl_xor_sync(0xffffffffu, m, off));
    float e = __expf(o - m), se = e;
#pragma unroll
    for (int off = 1; off < 16; off <<= 1)
        se += __shfl_xor_sync(0xffffffffu, se, off);
    out[(size_t)(n0 + nb) * NCLASS + c] = o - m - __logf(se);
}

// ============================================================
// K4: l1 loss = mean |W_fus|
// ============================================================
__global__ void k4_loss(const float* __restrict__ Wfus, float* __restrict__ out) {
    __shared__ float s[256];
    const int t = threadIdx.x;
    float v = 0.f;
    for (int i = t; i < NCLASS * NCLASS * NGRAPH; i += 256) v += fabsf(Wfus[i]);
    s[t] = v;
    __syncthreads();
    for (int st = 128; st > 0; st >>= 1) {
        if (t < st) s[t] += s[t + st];
        __syncthreads();
    }
    if (t == 0) out[N_NODES * NCLASS] = s[0] / (float)(NCLASS * NCLASS * NGRAPH);
}

// ============================================================
extern "C" void kernel_launch(void* const* d_in, const int* in_sizes, int n_in,
                              void* d_out, int out_size) {
    const float* x    = (const float*)d_in[0];
    const int*   adj  = (const int*)  d_in[1];
    const float* W    = (const float*)d_in[2];
    const float* a    = (const float*)d_in[3];
    const float* Wint = (const float*)d_in[4];
    const float* bint = (const float*)d_in[5];
    const float* Wfus = (const float*)d_in[6];
    const float* bfus = (const float*)d_in[7];
    float* out = (float*)d_out;

    const int K1_SMEM = (16384 + 128) * 4;   // 66048 B
    cudaFuncSetAttribute(k1_wh, cudaFuncAttributeMaxDynamicSharedMemorySize, K1_SMEM);

    k0_pack<<<NGRAPH * N_NODES / 8, 256>>>(adj);
    k0x<<<dim3(48, 8), 128>>>(x);
    k0w<<<dim3(NGH, 8), 128>>>(W);
    k1_wh<<<dim3(48, NGH), 128, K1_SMEM>>>(a);
    k2_attn<<<dim3(N_NODES / 64, NHEADS, NGRAPH), 128>>>();
    k3_out<<<N_NODES / 8, 128>>>(Wint, bint, Wfus, bfus, out);
    if (out_size > N_NODES * NCLASS)
        k4_loss<<<1, 256>>>(Wfus, out);
}

// round 15
// speedup vs baseline: 1.0724x; 1.0724x over previous
#include <cuda_runtime.h>
#include <math.h>
#include <stdint.h>

#define N_NODES 3072
#define F_IN 512
#define NHID 64
#define NHEADS 4
#define NGRAPH 3
#define NCLASS 16
#define NGH (NGRAPH * NHEADS)
#define DCAT (NHEADS * NHID)   // 256
#define ALPHA 0.2f

#define GEMM_BLOCKS (48 * NGH)            // 576
#define PACK_BLOCKS (NGRAPH * N_NODES / 4) // 2304

// -------- scratch (no allocations allowed) --------
__device__ uint32_t d_Whbf[NGH * 48 * 2048];                 // bf16x2, tile-swizzled
__device__ float2 d_ef1[NGH * N_NODES];                      // (e^f1, e^{0.2 f1})
__device__ float2 d_ef2[NGH * N_NODES];                      // (e^f2, e^{0.2 f2})
__device__ float d_hcat[NGRAPH * N_NODES * DCAT];            // [g][n][h*64+o]
__device__ unsigned long long d_abits[NGRAPH * N_NODES * 48]; // bitpacked adj

// ---------- helpers ----------
__device__ __forceinline__ uint32_t f2tf32(float f) {
    uint32_t u;
    asm("cvt.rna.tf32.f32 %0, %1;" : "=r"(u) : "f"(f));
    return u;
}
__device__ __forceinline__ uint32_t pkbf2(float lo, float hi) {
    uint32_t r;
    asm("cvt.rn.bf16x2.f32 %0, %1, %2;" : "=r"(r) : "f"(hi), "f"(lo));
    return r;
}
__device__ __forceinline__ void mma_tf32(float d[4], uint32_t a0, uint32_t a1,
                                         uint32_t a2, uint32_t a3,
                                         uint32_t b0, uint32_t b1) {
    asm volatile(
        "mma.sync.aligned.m16n8k8.row.col.f32.tf32.tf32.f32 "
        "{%0,%1,%2,%3},{%4,%5,%6,%7},{%8,%9},{%0,%1,%2,%3};\n"
        : "+f"(d[0]), "+f"(d[1]), "+f"(d[2]), "+f"(d[3])
        : "r"(a0), "r"(a1), "r"(a2), "r"(a3), "r"(b0), "r"(b1));
}
__device__ __forceinline__ void mma_bf16(float d[4], uint32_t a0, uint32_t a1,
                                         uint32_t a2, uint32_t a3,
                                         uint32_t b0, uint32_t b1) {
    asm volatile(
        "mma.sync.aligned.m16n8k16.row.col.f32.bf16.bf16.f32 "
        "{%0,%1,%2,%3},{%4,%5,%6,%7},{%8,%9},{%0,%1,%2,%3};\n"
        : "+f"(d[0]), "+f"(d[1]), "+f"(d[2]), "+f"(d[3])
        : "r"(a0), "r"(a1), "r"(a2), "r"(a3), "r"(b0), "r"(b1));
}
// word-granular swizzle: word (kp, n) of a [32|64]x64 word tile.
__device__ __forceinline__ int bswz(int k, int n) {
    return k * 64 + (n ^ ((k & 3) << 3));
}
__device__ __forceinline__ int aswz(int r, int c) {
    return r * 64 + (c ^ ((r & 3) << 3) ^ (r & 4));
}
// cp.async
__device__ __forceinline__ void cpa16(void* smem_dst, const void* gsrc) {
    uint32_t d = (uint32_t)__cvta_generic_to_shared(smem_dst);
    asm volatile("cp.async.ca.shared.global [%0], [%1], 16;\n" :: "r"(d), "l"(gsrc));
}
__device__ __forceinline__ void cpa_commit() {
    asm volatile("cp.async.commit_group;\n");
}
template <int NW> __device__ __forceinline__ void cpa_wait() {
    asm volatile("cp.async.wait_group %0;\n" :: "n"(NW));
}

// ============================================================
// K_FRONT: one launch, two independent block families:
//   blocks [0, 576):        Wh = x @ W (tf32 mma, inline cvt) + epilogue
//   blocks [576, 2880):     adj bitpack (4 rows / block)
// The DRAM-bound pack blocks overlap the tensor/LDS-bound GEMM blocks.
// ============================================================
__global__ __launch_bounds__(128) void k_front(const float* __restrict__ x,
                                               const float* __restrict__ W,
                                               const float* __restrict__ a,
                                               const int* __restrict__ adj) {
    __shared__ uint32_t As[4096];
    __shared__ uint32_t Bs[4096];
    __shared__ float sa[128];
    const int t = threadIdx.x;

    if (blockIdx.x >= GEMM_BLOCKS) {
        // ---------------- adj bitpack ----------------
        const int row = (blockIdx.x - GEMM_BLOCKS) * 4 + (t >> 5);  // g*N + n
        const int lane = t & 31;
        const int* arow = adj + (size_t)row * N_NODES;
        unsigned long long* brow = d_abits + (size_t)row * 48;
        for (int j = 0; j < 48; j++) {
            unsigned lo = __ballot_sync(0xffffffffu, arow[j * 64 + lane] != 0);
            unsigned hi = __ballot_sync(0xffffffffu, arow[j * 64 + 32 + lane] != 0);
            if (lane == 0) brow[j] = ((unsigned long long)hi << 32) | lo;
        }
        return;
    }

    // ---------------- Wh GEMM ----------------
    const int gh = blockIdx.x / 48, bx = blockIdx.x % 48;
    const int n0 = bx * 64;
    const int lane = t & 31, w = t >> 5;
    const int gi = lane >> 2, q = lane & 3;
    const float* Wg = W + (size_t)gh * F_IN * NHID;
    sa[t] = a[gh * 128 + t];

    float acc[8][4];
#pragma unroll
    for (int nt = 0; nt < 8; nt++)
#pragma unroll
        for (int j = 0; j < 4; j++) acc[nt][j] = 0.f;

    for (int k0 = 0; k0 < F_IN; k0 += 64) {
        __syncthreads();
#pragma unroll
        for (int it = 0; it < 8; it++) {
            int idx = t + it * 128;
            int r = idx >> 4, c4 = (idx & 15) * 4;
            float4 v = *(const float4*)(x + (size_t)(n0 + r) * F_IN + k0 + c4);
            int o = aswz(r, c4);
            As[o] = f2tf32(v.x); As[o + 1] = f2tf32(v.y);
            As[o + 2] = f2tf32(v.z); As[o + 3] = f2tf32(v.w);
        }
#pragma unroll
        for (int it = 0; it < 8; it++) {
            int idx = t + it * 128;
            int k = idx >> 4, n4 = (idx & 15) * 4;
            float4 v = *(const float4*)(Wg + (size_t)(k0 + k) * NHID + n4);
            int o = bswz(k, n4);
            Bs[o] = f2tf32(v.x); Bs[o + 1] = f2tf32(v.y);
            Bs[o + 2] = f2tf32(v.z); Bs[o + 3] = f2tf32(v.w);
        }
        __syncthreads();
#pragma unroll
        for (int kt = 0; kt < 8; kt++) {
            uint32_t a0 = As[aswz(16 * w + gi,     8 * kt + q)];
            uint32_t a1 = As[aswz(16 * w + gi + 8, 8 * kt + q)];
            uint32_t a2 = As[aswz(16 * w + gi,     8 * kt + q + 4)];
            uint32_t a3 = As[aswz(16 * w + gi + 8, 8 * kt + q + 4)];
#pragma unroll
            for (int nt = 0; nt < 8; nt++) {
                uint32_t b0 = Bs[bswz(8 * kt + q,     8 * nt + gi)];
                uint32_t b1 = Bs[bswz(8 * kt + q + 4, 8 * nt + gi)];
                mma_tf32(acc[nt], a0, a1, a2, a3, b0, b1);
            }
        }
    }

    const int R0 = n0 + 16 * w + gi, R1 = R0 + 8;

    // ---- f1/f2 (full-precision fragments), then exp forms ----
    float p10 = 0.f, p20 = 0.f, p11 = 0.f, p21 = 0.f;
#pragma unroll
    for (int nt = 0; nt < 8; nt++) {
        int c0 = 8 * nt + 2 * q;
        p10 += acc[nt][0] * sa[c0]      + acc[nt][1] * sa[c0 + 1];
        p20 += acc[nt][0] * sa[64 + c0] + acc[nt][1] * sa[64 + c0 + 1];
        p11 += acc[nt][2] * sa[c0]      + acc[nt][3] * sa[c0 + 1];
        p21 += acc[nt][2] * sa[64 + c0] + acc[nt][3] * sa[64 + c0 + 1];
    }
#pragma unroll
    for (int off = 1; off < 4; off <<= 1) {
        p10 += __shfl_xor_sync(0xffffffffu, p10, off);
        p20 += __shfl_xor_sync(0xffffffffu, p20, off);
        p11 += __shfl_xor_sync(0xffffffffu, p11, off);
        p21 += __shfl_xor_sync(0xffffffffu, p21, off);
    }
    if (q == 0) {
        d_ef1[(size_t)gh * N_NODES + R0] = make_float2(__expf(p10), __expf(ALPHA * p10));
        d_ef2[(size_t)gh * N_NODES + R0] = make_float2(__expf(p20), __expf(ALPHA * p20));
        d_ef1[(size_t)gh * N_NODES + R1] = make_float2(__expf(p11), __expf(ALPHA * p11));
        d_ef2[(size_t)gh * N_NODES + R1] = make_float2(__expf(p21), __expf(ALPHA * p21));
    }

    // ---- bf16 pack, adjacent-row pairing via shfl, swizzled store ----
    uint32_t* dst = d_Whbf + ((size_t)gh * 48 + bx) * 2048;
    const bool even = (gi & 1) == 0;
    const int kp = 8 * w + (gi >> 1) + (even ? 0 : 4);
#pragma unroll
    for (int nt = 0; nt < 8; nt++) {
        float o0 = __shfl_xor_sync(0xffffffffu, acc[nt][0], 4);
        float o1 = __shfl_xor_sync(0xffffffffu, acc[nt][1], 4);
        float o2 = __shfl_xor_sync(0xffffffffu, acc[nt][2], 4);
        float o3 = __shfl_xor_sync(0xffffffffu, acc[nt][3], 4);
        uint32_t w0, w1;
        if (even) { w0 = pkbf2(acc[nt][0], o0); w1 = pkbf2(acc[nt][1], o1); }
        else      { w0 = pkbf2(o2, acc[nt][2]); w1 = pkbf2(o3, acc[nt][3]); }
        int c = 8 * nt + 2 * q;
        int o = bswz(kp, c);
        *(uint2*)&dst[o] = make_uint2(w0, w1);
    }
}

// ============================================================
// K2: fused attention. exp(leaky(s)) = max(ea*eb, fa*fb) -- zero MUFU
// in the hot loop. cp.async double-buffered staging of pre-packed bf16 Wh.
// grid (48, NHEADS, NGRAPH), 128 thr.
// ============================================================
__global__ __launch_bounds__(128) void k2_attn() {
    __shared__ uint32_t Whs[2][2048];
    __shared__ float2 efs[2][64];
    const int g_ = blockIdx.z, h = blockIdx.y;
    const int gh = g_ * NHEADS + h;
    const int n0 = blockIdx.x * 64;
    const int t = threadIdx.x, lane = t & 31, w = t >> 5;
    const int gi = lane >> 2, q = lane & 3;
    const int qx = q << 3;
    const int R0 = n0 + 16 * w + gi, R1 = R0 + 8;

    const uint32_t* Wsrc = d_Whbf + (size_t)gh * 48 * 2048;
    const float2* ef2g = d_ef2 + (size_t)gh * N_NODES;
    const unsigned long long* bits0 = d_abits + ((size_t)g_ * N_NODES + R0) * 48;
    const unsigned long long* bits1 = d_abits + ((size_t)g_ * N_NODES + R1) * 48;
    const float2 ef1a = d_ef1[(size_t)gh * N_NODES + R0];
    const float2 ef1b = d_ef1[(size_t)gh * N_NODES + R1];
    const float ea0 = ef1a.x, fa0 = ef1a.y, ea1 = ef1b.x, fa1 = ef1b.y;

    int nxs[8];
#pragma unroll
    for (int nt = 0; nt < 8; nt++) nxs[nt] = (8 * nt + gi) ^ qx;

    float acc[8][4];
#pragma unroll
    for (int nt = 0; nt < 8; nt++)
#pragma unroll
        for (int j = 0; j < 4; j++) acc[nt][j] = 0.f;
    float rs0 = 0.f, rs1 = 0.f;

    // stage tile 0
    {
        const uint32_t* src = Wsrc;
#pragma unroll
        for (int it = 0; it < 4; it++)
            cpa16(&Whs[0][(t + it * 128) * 4], src + (t + it * 128) * 4);
        if (t < 32) cpa16(&efs[0][t * 2], ef2g + t * 2);
        cpa_commit();
    }

    for (int mt = 0; mt < 48; mt++) {
        const int buf = mt & 1;
        if (mt + 1 < 48) {
            const uint32_t* src = Wsrc + (size_t)(mt + 1) * 2048;
#pragma unroll
            for (int it = 0; it < 4; it++)
                cpa16(&Whs[buf ^ 1][(t + it * 128) * 4], src + (t + it * 128) * 4);
            if (t < 32) cpa16(&efs[buf ^ 1][t * 2], ef2g + (mt + 1) * 64 + t * 2);
            cpa_commit();
            cpa_wait<1>();
        } else {
            cpa_wait<0>();
        }
        __syncthreads();

        const uint32_t m0lo = (uint32_t)bits0[mt], m0hi = (uint32_t)(bits0[mt] >> 32);
        const uint32_t m1lo = (uint32_t)bits1[mt], m1hi = (uint32_t)(bits1[mt] >> 32);

#pragma unroll
        for (int kt = 0; kt < 4; kt++) {
            const int cb = 16 * kt + 2 * q;
            const float2 e0 = efs[buf][cb],     e1 = efs[buf][cb + 1];
            const float2 e8 = efs[buf][cb + 8], e9 = efs[buf][cb + 9];
            const uint32_t m0b = (kt < 2) ? (m0lo >> cb) : (m0hi >> (cb - 32));
            const uint32_t m1b = (kt < 2) ? (m1lo >> cb) : (m1hi >> (cb - 32));

            float p00 = fmaxf(ea0 * e0.x, fa0 * e0.y);
            float p01 = fmaxf(ea0 * e1.x, fa0 * e1.y);
            float p02 = fmaxf(ea0 * e8.x, fa0 * e8.y);
            float p03 = fmaxf(ea0 * e9.x, fa0 * e9.y);
            float p10 = fmaxf(ea1 * e0.x, fa1 * e0.y);
            float p11 = fmaxf(ea1 * e1.x, fa1 * e1.y);
            float p12 = fmaxf(ea1 * e8.x, fa1 * e8.y);
            float p13 = fmaxf(ea1 * e9.x, fa1 * e9.y);

            p00 = (m0b & 1u)     ? p00 : 0.f;
            p01 = (m0b & 2u)     ? p01 : 0.f;
            p02 = (m0b & 0x100u) ? p02 : 0.f;
            p03 = (m0b & 0x200u) ? p03 : 0.f;
            p10 = (m1b & 1u)     ? p10 : 0.f;
            p11 = (m1b & 2u)     ? p11 : 0.f;
            p12 = (m1b & 0x100u) ? p12 : 0.f;
            p13 = (m1b & 0x200u) ? p13 : 0.f;

            rs0 += (p00 + p01) + (p02 + p03);
            rs1 += (p10 + p11) + (p12 + p13);

            const uint32_t a0 = pkbf2(p00, p01);
            const uint32_t a1 = pkbf2(p10, p11);
            const uint32_t a2 = pkbf2(p02, p03);
            const uint32_t a3 = pkbf2(p12, p13);
            const int kb0 = (8 * kt + q) * 64;
            const int kb1 = kb0 + 256;
#pragma unroll
            for (int nt = 0; nt < 8; nt++) {
                uint32_t b0 = Whs[buf][kb0 + nxs[nt]];
                uint32_t b1 = Whs[buf][kb1 + nxs[nt]];
                mma_bf16(acc[nt], a0, a1, a2, a3, b0, b1);
            }
        }
        __syncthreads();
    }

    rs0 += __shfl_xor_sync(0xffffffffu, rs0, 1);
    rs0 += __shfl_xor_sync(0xffffffffu, rs0, 2);
    rs1 += __shfl_xor_sync(0xffffffffu, rs1, 1);
    rs1 += __shfl_xor_sync(0xffffffffu, rs1, 2);

    const float inv0 = 1.0f / rs0, inv1 = 1.0f / rs1;
    float* outg = d_hcat + (size_t)g_ * N_NODES * DCAT;
#pragma unroll
    for (int nt = 0; nt < 8; nt++) {
        float v0 = acc[nt][0] * inv0, v1 = acc[nt][1] * inv0;
        float v2 = acc[nt][2] * inv1, v3 = acc[nt][3] * inv1;
        v0 = v0 > 0.f ? v0 : (__expf(v0) - 1.f);
        v1 = v1 > 0.f ? v1 : (__expf(v1) - 1.f);
        v2 = v2 > 0.f ? v2 : (__expf(v2) - 1.f);
        v3 = v3 > 0.f ? v3 : (__expf(v3) - 1.f);
        *(float2*)(outg + (size_t)R0 * DCAT + h * NHID + 8 * nt + 2 * q) =
            make_float2(v0, v1);
        *(float2*)(outg + (size_t)R1 * DCAT + h * NHID + 8 * nt + 2 * q) =
            make_float2(v2, v3);
    }
}

// ============================================================
// K3: xi = elu(hcat @ W_int^T + b_int) -> @ W_fus^T + b_fus -> log_softmax
// cp.async stages weights AND the block's 8 hcat rows into smem.
// Block 384 (if present) computes the l1 loss (fused old k4).
// ============================================================
__global__ __launch_bounds__(128) void k3_out(const float* __restrict__ Wint,
                                              const float* __restrict__ bint,
                                              const float* __restrict__ Wfus,
                                              const float* __restrict__ bfus,
                                              float* __restrict__ out) {
    __shared__ __align__(16) float sWi[NCLASS][260];   // natural [c][k]
    __shared__ __align__(16) float sWf[NCLASS * 52];
    __shared__ __align__(16) float sh[NGRAPH][8][DCAT];
    __shared__ float sXi[8 * 48];
    __shared__ float sbi[NCLASS], sbf[NCLASS];
    const int t = threadIdx.x;

    if (blockIdx.x == 384) {
        // ---- l1 loss = mean |W_fus| ----
        float v = 0.f;
        for (int i = t; i < NCLASS * NCLASS * NGRAPH; i += 128) v += fabsf(Wfus[i]);
        sXi[t] = v;
        __syncthreads();
        for (int st = 64; st > 0; st >>= 1) {
            if (t < st) sXi[t] += sXi[t + st];
            __syncthreads();
        }
        if (t == 0) out[N_NODES * NCLASS] = sXi[0] / (float)(NCLASS * NCLASS * NGRAPH);
        return;
    }

    const int n0 = blockIdx.x * 8;

    // stage everything with one cp.async wave
    for (int s = t; s < 1024; s += 128) {          // W_int: 16x256
        int c = s >> 6, ks = (s & 63) * 4;
        cpa16(&sWi[c][ks], Wint + c * DCAT + ks);
    }
    for (int s = t; s < 192; s += 128) {           // W_fus: 16x48
        int c = s / 12, js = (s % 12) * 4;
        cpa16(&sWf[c * 52 + js], Wfus + c * 48 + js);
    }
    for (int s = t; s < 1536; s += 128) {          // hcat: 3 x 8 x 256
        int g = s / 512, rem = s - g * 512;
        int node = rem >> 6, ks = (rem & 63) * 4;
        cpa16(&sh[g][node][ks],
              d_hcat + ((size_t)g * N_NODES + n0 + node) * DCAT + ks);
    }
    cpa_commit();
    if (t < NCLASS) { sbi[t] = bint[t]; sbf[t] = bfus[t]; }
    cpa_wait<0>();
    __syncthreads();

    const int nb = t >> 4, c = t & 15;
    const float* wc = sWi[c];

#pragma unroll
    for (int g = 0; g < NGRAPH; g++) {
        const float* hp = sh[g][nb];
        float a0 = 0.f, a1 = 0.f, a2 = 0.f, a3 = 0.f;
#pragma unroll 4
        for (int k0 = 0; k0 < DCAT; k0 += 16) {
            float4 h0 = *(const float4*)(hp + k0);
            float4 h1 = *(const float4*)(hp + k0 + 4);
            float4 h2 = *(const float4*)(hp + k0 + 8);
            float4 h3 = *(const float4*)(hp + k0 + 12);
            float4 w0 = *(const float4*)(wc + k0);
            float4 w1 = *(const float4*)(wc + k0 + 4);
            float4 w2 = *(const float4*)(wc + k0 + 8);
            float4 w3 = *(const float4*)(wc + k0 + 12);
            a0 += h0.x * w0.x + h0.y * w0.y + h0.z * w0.z + h0.w * w0.w;
            a1 += h1.x * w1.x + h1.y * w1.y + h1.z * w1.z + h1.w * w1.w;
            a2 += h2.x * w2.x + h2.y * w2.y + h2.z * w2.z + h2.w * w2.w;
            a3 += h3.x * w3.x + h3.y * w3.y + h3.z * w3.z + h3.w * w3.w;
        }
        float xv = (a0 + a1) + (a2 + a3) + sbi[c];
        sXi[nb * 48 + g * 16 + c] = xv > 0.f ? xv : (__expf(xv) - 1.f);
    }
    __syncthreads();

    float o = sbf[c];
#pragma unroll
    for (int j = 0; j < 48; j++) o += sXi[nb * 48 + j] * sWf[c * 52 + j];

    float m = o;
#pragma unroll
    for (int off = 1; off < 16; off <<= 1)
        m = fmaxf(m, __shfl_xor_sync(0xffffffffu, m, off));
    float e = __expf(o - m), se = e;
#pragma unroll
    for (int off = 1; off < 16; off <<= 1)
        se += __shfl_xor_sync(0xffffffffu, se, off);
    out[(size_t)(n0 + nb) * NCLASS + c] = o - m - __logf(se);
}

// ============================================================
extern "C" void kernel_launch(void* const* d_in, const int* in_sizes, int n_in,
                              void* d_out, int out_size) {
    const float* x    = (const float*)d_in[0];
    const int*   adj  = (const int*)  d_in[1];
    const float* W    = (const float*)d_in[2];
    const float* a    = (const float*)d_in[3];
    const float* Wint = (const float*)d_in[4];
    const float* bint = (const float*)d_in[5];
    const float* Wfus = (const float*)d_in[6];
    const float* bfus = (const float*)d_in[7];
    float* out = (float*)d_out;

    k_front<<<GEMM_BLOCKS + PACK_BLOCKS, 128>>>(x, W, a, adj);
    k2_attn<<<dim3(N_NODES / 64, NHEADS, NGRAPH), 128>>>();
    const int g3 = 384 + (out_size > N_NODES * NCLASS ? 1 : 0);
    k3_out<<<g3, 128>>>(Wint, bint, Wfus, bfus, out);
}